// round 12
// baseline (speedup 1.0000x reference)
#include <cuda_runtime.h>
#include <cuda.h>
#include <cstdint>

// Router_63900523430579 (GB300/sm_103): scores = x[32768,2048] @ W[64,2048]^T
// Fused persistent kernel. Staging via TMA (cp.async.bulk.tensor.2d for x,
// cp.async.bulk 1D for fragment-packed W) -> mma.sync tf32 -> top-2 epilogue,
// grid barrier, fp64 fixup of ambiguous tokens + aux loss.
// out f32: [0,65536) top2 idx ; [65536,131072) top2 weights ; [131072] aux loss

#define KDIM   2048
#define NTOK   32768
#define NEXP   64
#define MTILE  128
#define NCTA   (NTOK / MTILE)          // 256
#define NTHR   256
#define CK     32                      // K floats per chunk (128 B)
#define NCHUNK (KDIM / CK)             // 64
#define XB     (MTILE * 128)           // 16384 B x per stage (swizzled rows)
#define WBYTES 8192                    // packed W per chunk
#define STAGEB (XB + WBYTES)           // 24576 B
#define NSTAGE 4
#define SMEM_REQ (NSTAGE * STAGEB + 1024)   // 99328 B -> 2 CTA/SM
#define TXBYTES ((unsigned)STAGEB)
#define DELTA1 3.0e-3f

__device__ int      g_done, g_done2, g_cnt1, g_cnt2;
__device__ float    g_Wp[NEXP * KDIM];          // fragment-packed W
__device__ float    g_part[NCTA * NEXP];
__device__ int      g_list1[NTOK], g_list2[NTOK];
__device__ unsigned g_cand[NTOK];

__device__ __forceinline__ void mma8(float* d, uint32_t a0, uint32_t a1,
                                     uint32_t a2, uint32_t a3,
                                     uint32_t b0, uint32_t b1) {
    asm volatile("mma.sync.aligned.m16n8k8.row.col.f32.tf32.tf32.f32 "
                 "{%0,%1,%2,%3},{%4,%5,%6,%7},{%8,%9},{%0,%1,%2,%3};"
                 : "+f"(d[0]), "+f"(d[1]), "+f"(d[2]), "+f"(d[3])
                 : "r"(a0), "r"(a1), "r"(a2), "r"(a3), "r"(b0), "r"(b1));
}
#define MBARRIER_INIT(m, c) \
    asm volatile("mbarrier.init.shared.b64 [%0], %1;" \
                 :: "r"((uint32_t)(m)), "r"((uint32_t)(c)) : "memory")
#define MBARRIER_EXPECT_TX(m, b) \
    asm volatile("mbarrier.arrive.expect_tx.shared.b64 _, [%0], %1;" \
                 :: "r"((uint32_t)(m)), "r"((uint32_t)(b)) : "memory")
#define MBAR_WAIT(m, p) do { \
    uint32_t _m = (uint32_t)(m), _p = (uint32_t)(p), _d; \
    asm volatile("{\n\t.reg .pred q;\n\t" \
        "mbarrier.try_wait.parity.acquire.cta.shared::cta.b64 q, [%1], %2;\n\t" \
        "selp.b32 %0, 1, 0, q;\n\t}" : "=r"(_d) : "r"(_m), "r"(_p) : "memory"); \
    if (!_d) { \
        asm volatile("{\n\t.reg .pred P1;\n\t" \
            "WL_%=:\n\t" \
            "mbarrier.try_wait.parity.acquire.cta.shared::cta.b64 P1, [%0], %1, 0x989680;\n\t" \
            "@P1 bra.uni WD_%=;\n\t" \
            "bra.uni WL_%=;\n\t" \
            "WD_%=:\n\t}" :: "r"(_m), "r"(_p) : "memory"); \
    } } while (0)
__device__ __forceinline__ void tma_load_2d(uint32_t dst, const void* map,
                                            int cx, int cy, uint32_t mbar) {
    asm volatile("cp.async.bulk.tensor.2d.shared::cta.global.tile.mbarrier::complete_tx::bytes "
                 "[%0], [%1, {%2, %3}], [%4];"
                 :: "r"(dst), "l"(map), "r"(cx), "r"(cy), "r"(mbar) : "memory");
}
__device__ __forceinline__ void bulk_load_1d(uint32_t dst, const void* src,
                                             uint32_t bytes, uint32_t mbar) {
    asm volatile("cp.async.bulk.shared::cluster.global.mbarrier::complete_tx::bytes "
                 "[%0], [%1], %2, [%3];"
                 :: "r"(dst), "l"(src), "r"(bytes), "r"(mbar) : "memory");
}

// ---- prep: pack W into per-chunk fragment-contiguous layout + reset ----
// pos(c,s,j,t,p) = c*2048 + (s*8+j)*64 + t*2 + p  holds
//   W[e = j*8 + t/4][k = c*32 + s*8 + (t&3) + 4p]
__global__ void prep_kernel(const float* __restrict__ W) {
    int pi = blockIdx.x * blockDim.x + threadIdx.x;     // 65536 pairs
    if (pi < NEXP * KDIM / 2) {
        int c = pi >> 10, rem = pi & 1023;
        int sj = rem >> 5, t = rem & 31;
        int e = (sj & 7) * 8 + (t >> 2);
        int k = c * 32 + (sj >> 3) * 8 + (t & 3);
        g_Wp[2 * pi]     = W[(size_t)e * KDIM + k];
        g_Wp[2 * pi + 1] = W[(size_t)e * KDIM + k + 4];
    }
    if (pi == 0) { g_done = 0; g_done2 = 0; g_cnt1 = 0; g_cnt2 = 0; }
}

__global__ void __launch_bounds__(NTHR, 2)
fused_kernel(const __grid_constant__ CUtensorMap tmap,
             const float* __restrict__ x, const float* __restrict__ W,
             float* __restrict__ out) {
    extern __shared__ float smraw[];
    __shared__ __align__(8) unsigned long long mbar_st[NSTAGE];
    const uint32_t rawb = (uint32_t)__cvta_generic_to_shared(smraw);
    const uint32_t base = (rawb + 1023u) & ~1023u;          // 1024-align for SW128
    float* sm = smraw + (base - rawb) / 4;
    const uint32_t mb0 = (uint32_t)__cvta_generic_to_shared(mbar_st);
    const int tid = threadIdx.x;
    const int wid = tid >> 5, lane = tid & 31;
    const int lq = lane & 3, lr = lane >> 2;

    // ================= PHASE A: GEMM tile =================
    if (tid == 0) {
        #pragma unroll
        for (int s = 0; s < NSTAGE; s++) MBARRIER_INIT(mb0 + 8 * s, 1);
    }
    __syncthreads();

    auto issue_chunk = [&](int c) {
        int st = c & (NSTAGE - 1);
        uint32_t xdst = base + (uint32_t)st * STAGEB;
        MBARRIER_EXPECT_TX(mb0 + 8 * st, TXBYTES);
        tma_load_2d(xdst, &tmap, c * CK, blockIdx.x * MTILE, mb0 + 8 * st);
        bulk_load_1d(xdst + XB, g_Wp + (size_t)c * 2048, WBYTES, mb0 + 8 * st);
    };

    float acc[8][4];
    #pragma unroll
    for (int j = 0; j < 8; j++)
        #pragma unroll
        for (int v = 0; v < 4; v++) acc[j][v] = 0.0f;

    if (tid == 0) { issue_chunk(0); issue_chunk(1); issue_chunk(2); issue_chunk(3); }

    const int r0 = wid * 16 + lr;       // a-frag rows r0, r0+8 ; r&7 == lr
    for (int c = 0; c < NCHUNK; c++) {
        const int st = c & (NSTAGE - 1);
        MBAR_WAIT(mb0 + 8 * st, (c >> 2) & 1);

        const float* xb = sm + st * (STAGEB / 4);
        const float* wb = xb + XB / 4;
        #pragma unroll
        for (int s = 0; s < 4; s++) {
            // swizzled x reads: float idx = r*32 + (g ^ lr)*4 + lq, g = 2s / 2s+1
            const int g0 = ((2 * s)     ^ lr) * 4 + lq;
            const int g1 = ((2 * s + 1) ^ lr) * 4 + lq;
            uint32_t a0 = __float_as_uint(xb[r0 * 32 + g0]);
            uint32_t a1 = __float_as_uint(xb[(r0 + 8) * 32 + g0]);
            uint32_t a2 = __float_as_uint(xb[r0 * 32 + g1]);
            uint32_t a3 = __float_as_uint(xb[(r0 + 8) * 32 + g1]);
            #pragma unroll
            for (int j = 0; j < 8; j++) {
                float2 b = *(const float2*)(wb + (s * 8 + j) * 64 + lane * 2);
                mma8(acc[j], a0, a1, a2, a3,
                     __float_as_uint(b.x), __float_as_uint(b.y));
            }
        }
        __syncthreads();                 // all warps done with stage st
        if (tid == 0 && c + NSTAGE < NCHUNK) issue_chunk(c + NSTAGE);
    }
    __syncthreads();

    // ---- epilogue overlay: sc[128][65], mm[128], iz[128], red[4][64] ----
    float* sc = sm;
    float* mm = sc + 128 * 65;
    float* iz = mm + 128;
    float* red = iz + 128;

    #pragma unroll
    for (int j = 0; j < 8; j++) {
        sc[r0 * 65 + j * 8 + 2 * lq]           = acc[j][0];
        sc[r0 * 65 + j * 8 + 2 * lq + 1]       = acc[j][1];
        sc[(r0 + 8) * 65 + j * 8 + 2 * lq]     = acc[j][2];
        sc[(r0 + 8) * 65 + j * 8 + 2 * lq + 1] = acc[j][3];
    }
    __syncthreads();

    if (tid < 128) {    // one token per thread: top-4, softmax, ambiguity routing
        const int t = tid;
        const float* row = sc + t * 65;
        float m[4] = {-3e38f, -3e38f, -3e38f, -3e38f};
        int   id[4] = {0, 0, 0, 0};
        #pragma unroll 8
        for (int e = 0; e < 64; e++) {
            float v = row[e];
            if (v > m[0])      { m[3]=m[2]; id[3]=id[2]; m[2]=m[1]; id[2]=id[1];
                                 m[1]=m[0]; id[1]=id[0]; m[0]=v; id[0]=e; }
            else if (v > m[1]) { m[3]=m[2]; id[3]=id[2]; m[2]=m[1]; id[2]=id[1];
                                 m[1]=v; id[1]=e; }
            else if (v > m[2]) { m[3]=m[2]; id[3]=id[2]; m[2]=v; id[2]=e; }
            else if (v > m[3]) { m[3]=v; id[3]=e; }
        }
        float Z = 0.0f;
        #pragma unroll 8
        for (int e = 0; e < 64; e++) Z += __expf(row[e] - m[0]);
        mm[t] = m[0];
        iz[t] = 1.0f / Z;

        float e2 = __expf(m[1] - m[0]);
        float w1 = 1.0f / (1.0f + e2);
        size_t T = (size_t)blockIdx.x * MTILE + t;
        out[2 * T]     = (float)id[0];
        out[2 * T + 1] = (float)id[1];
        out[2 * (size_t)NTOK + 2 * T]     = w1;
        out[2 * (size_t)NTOK + 2 * T + 1] = e2 * w1;

        if ((m[0] - m[1]) < DELTA1 || (m[1] - m[2]) < DELTA1) {
            if ((m[1] - m[3]) < DELTA1) {
                int q = atomicAdd(&g_cnt2, 1);
                g_list2[q] = (int)T;
            } else {
                int q = atomicAdd(&g_cnt1, 1);
                g_list1[q] = (int)T;
                g_cand[q] = (unsigned)id[0] | ((unsigned)id[1] << 8) |
                            ((unsigned)id[2] << 16) | ((unsigned)id[3] << 24);
            }
        }
    }
    __syncthreads();

    {   // deterministic per-CTA expert-usage partials (4 segs x 32 tokens)
        const int e = tid & 63, seg = tid >> 6;
        float s = 0.0f;
        for (int t = seg * 32; t < seg * 32 + 32; t++)
            s += __expf(sc[t * 65 + e] - mm[t]) * iz[t];
        red[seg * 64 + e] = s;
    }
    __syncthreads();
    if (tid < NEXP)
        g_part[blockIdx.x * NEXP + tid] =
            red[tid] + red[64 + tid] + red[128 + tid] + red[192 + tid];

    // ================= grid-wide barrier =================
    __threadfence();
    __syncthreads();
    if (tid == 0) {
        atomicAdd(&g_done, 1);
        while (atomicAdd(&g_done, 0) < NCTA) __nanosleep(128);
    }
    __syncthreads();
    __threadfence();

    // ================= PHASE B =================
    if (blockIdx.x == 0) {   // aux loss
        const int e = tid & 63, qtr = tid >> 6;
        float s = 0.0f;
        for (int c = qtr * 64; c < qtr * 64 + 64; c++)
            s += g_part[c * NEXP + e];
        sm[tid] = s;
        __syncthreads();
        if (tid < 64) {
            float u = (sm[tid] + sm[64 + tid] + sm[128 + tid] + sm[192 + tid])
                      * (1.0f / (float)NTOK);
            sm[256 + tid] = u * u;
        }
        __syncthreads();
        if (tid < 32) {
            float v = sm[256 + tid] + sm[256 + tid + 32];
            #pragma unroll
            for (int o = 16; o > 0; o >>= 1) v += __shfl_xor_sync(0xffffffffu, v, o);
            if (tid == 0) out[131072] = 64.0f * v;
        }
        __syncthreads();
    }

    // fp64 recompute of top-4 candidates: warps 0-3 -> token base, 4-7 -> base+NCTA
    {
        static __shared__ double sv[8];
        static __shared__ int    se[8];
        const int n = g_cnt1;
        for (int bq = blockIdx.x; bq < n; bq += 2 * NCTA) {
            const int q = bq + ((wid >= 4) ? NCTA : 0);
            const bool valid = (q < n);
            int tok = 0, e = 0;
            double s = 0.0;
            if (valid) {
                tok = g_list1[q];
                e = (int)((g_cand[q] >> (8 * (wid & 3))) & 255u);
                const float* xr = x + (size_t)tok * KDIM;
                const float* wr = W + (size_t)e * KDIM;
                double c0 = 0.0, c1 = 0.0, c2 = 0.0, c3 = 0.0;
                #pragma unroll 4
                for (int j = 0; j < 64; j += 4) {
                    c0 += (double)xr[(j + 0) * 32 + lane] * (double)wr[(j + 0) * 32 + lane];
                    c1 += (double)xr[(j + 1) * 32 + lane] * (double)wr[(j + 1) * 32 + lane];
                    c2 += (double)xr[(j + 2) * 32 + lane] * (double)wr[(j + 2) * 32 + lane];
                    c3 += (double)xr[(j + 3) * 32 + lane] * (double)wr[(j + 3) * 32 + lane];
                }
                s = (c0 + c1) + (c2 + c3);
            }
            #pragma unroll
            for (int o = 16; o > 0; o >>= 1) s += __shfl_xor_sync(0xffffffffu, s, o);
            if (lane == 0) { sv[wid] = s; se[wid] = e; }
            __syncthreads();
            if ((tid & 127) == 0) {
                const int g = tid >> 7;
                const int qq = bq + g * NCTA;
                if (qq < n) {
                    const int tk = g_list1[qq];
                    const double* v = sv + g * 4;
                    const int*    ee = se + g * 4;
                    int b1 = 0;
                    for (int k = 1; k < 4; k++)
                        if (v[k] > v[b1] || (v[k] == v[b1] && ee[k] < ee[b1])) b1 = k;
                    int b2 = (b1 == 0) ? 1 : 0;
                    for (int k = 0; k < 4; k++) {
                        if (k == b1) continue;
                        if (v[k] > v[b2] || (v[k] == v[b2] && ee[k] < ee[b2])) b2 = k;
                    }
                    double e2 = exp(v[b2] - v[b1]);
                    double w1 = 1.0 / (1.0 + e2);
                    out[2 * (size_t)tk]     = (float)ee[b1];
                    out[2 * (size_t)tk + 1] = (float)ee[b2];
                    out[2 * (size_t)NTOK + 2 * (size_t)tk]     = (float)w1;
                    out[2 * (size_t)NTOK + 2 * (size_t)tk + 1] = (float)(e2 * w1);
                }
            }
            __syncthreads();
        }
    }

    // rare full-64 fp64 tokens: warp wi -> experts wi*8..wi*8+7
    {
        static __shared__ double sh[64];
        const int n2 = g_cnt2;
        for (int q = blockIdx.x; q < n2; q += NCTA) {
            const int tok = g_list2[q];
            const float* xr = x + (size_t)tok * KDIM;
            #pragma unroll 1
            for (int e8 = 0; e8 < 8; e8++) {
                const int e = wid * 8 + e8;
                const float* wr = W + (size_t)e * KDIM;
                double c0 = 0.0, c1 = 0.0, c2 = 0.0, c3 = 0.0;
                #pragma unroll 4
                for (int j = 0; j < 64; j += 4) {
                    c0 += (double)xr[(j + 0) * 32 + lane] * (double)wr[(j + 0) * 32 + lane];
                    c1 += (double)xr[(j + 1) * 32 + lane] * (double)wr[(j + 1) * 32 + lane];
                    c2 += (double)xr[(j + 2) * 32 + lane] * (double)wr[(j + 2) * 32 + lane];
                    c3 += (double)xr[(j + 3) * 32 + lane] * (double)wr[(j + 3) * 32 + lane];
                }
                double s = (c0 + c1) + (c2 + c3);
                #pragma unroll
                for (int o = 16; o > 0; o >>= 1) s += __shfl_xor_sync(0xffffffffu, s, o);
                if (lane == 0) sh[e] = s;
            }
            __syncthreads();
            if (tid == 0) {
                double m1 = -1e300, m2 = -1e300; int i1 = 0, i2 = 0;
                for (int e = 0; e < 64; e++)
                    if (sh[e] > m1) { m1 = sh[e]; i1 = e; }
                for (int e = 0; e < 64; e++) {
                    if (e == i1) continue;
                    if (sh[e] > m2) { m2 = sh[e]; i2 = e; }
                }
                double e2 = exp(m2 - m1);
                double w1 = 1.0 / (1.0 + e2);
                out[2 * (size_t)tok]     = (float)i1;
                out[2 * (size_t)tok + 1] = (float)i2;
                out[2 * (size_t)NTOK + 2 * (size_t)tok]     = (float)w1;
                out[2 * (size_t)NTOK + 2 * (size_t)tok + 1] = (float)(e2 * w1);
            }
            __syncthreads();
        }
    }

    // ================= PHASE C: reset for next graph replay =================
    __syncthreads();
    if (tid == 0) {
        __threadfence();
        int v = atomicAdd(&g_done2, 1);
        if (v == NCTA - 1) {
            g_done = 0; g_done2 = 0; g_cnt1 = 0; g_cnt2 = 0;
            __threadfence();
        }
    }
}

typedef CUresult (*EncodeTiledFn)(
    CUtensorMap*, CUtensorMapDataType, cuuint32_t, void*,
    const cuuint64_t*, const cuuint64_t*, const cuuint32_t*, const cuuint32_t*,
    CUtensorMapInterleave, CUtensorMapSwizzle, CUtensorMapL2promotion,
    CUtensorMapFloatOOBfill);

extern "C" void kernel_launch(void* const* d_in, const int* in_sizes, int n_in,
                              void* d_out, int out_size) {
    const float* x = (const float*)d_in[0];
    const float* W = (const float*)d_in[1];
    float* out = (float*)d_out;

    // Build tensor map for x: inner dim KDIM floats (contiguous), outer NTOK rows.
    CUtensorMap tmap;
    {
        void* fp = nullptr;
        cudaDriverEntryPointQueryResult qr;
        cudaGetDriverEntryPoint("cuTensorMapEncodeTiled", &fp,
                                cudaEnableDefault, &qr);
        EncodeTiledFn enc = (EncodeTiledFn)fp;
        cuuint64_t dims[2]    = {KDIM, NTOK};
        cuuint64_t strides[1] = {KDIM * sizeof(float)};
        cuuint32_t box[2]     = {CK, MTILE};
        cuuint32_t estr[2]    = {1, 1};
        enc(&tmap, CU_TENSOR_MAP_DATA_TYPE_FLOAT32, 2, (void*)x,
            dims, strides, box, estr,
            CU_TENSOR_MAP_INTERLEAVE_NONE, CU_TENSOR_MAP_SWIZZLE_128B,
            CU_TENSOR_MAP_L2_PROMOTION_L2_128B,
            CU_TENSOR_MAP_FLOAT_OOB_FILL_NONE);
    }

    cudaFuncSetAttribute(fused_kernel, cudaFuncAttributeMaxDynamicSharedMemorySize,
                         SMEM_REQ);
    prep_kernel<<<256, 256>>>(W);
    fused_kernel<<<NCTA, NTHR, SMEM_REQ>>>(tmap, x, W, out);
}

// round 14
// speedup vs baseline: 1.4350x; 1.4350x over previous
#include <cuda_runtime.h>
#include <cstdint>

// Router_63900523430579 (GB300/sm_103): scores = x[32768,2048] @ W[64,2048]^T
// Fused persistent kernel, 512 thr (16 warps, 64 regs/thr -> 32 warps/SM).
// tf32 mma.sync GEMM (fragment-packed W) + top-2 epilogue, grid barrier,
// fp64 fixup of ambiguous tokens + aux loss.
// out f32: [0,65536) top2 idx ; [65536,131072) top2 weights ; [131072] aux loss

#define KDIM   2048
#define NTOK   32768
#define NEXP   64
#define MTILE  128
#define NCTA   (NTOK / MTILE)          // 256
#define NTHR   512
#define CK     32
#define NCHUNK (KDIM / CK)             // 64
#define RWX    36                      // x row stride (floats), conflict-free
#define XB     (MTILE * RWX * 4)       // 18432 B x per stage
#define WBYTES 8192                    // packed W per chunk
#define STAGEB (XB + WBYTES)           // 26624 B
#define STAGEW (STAGEB / 4)
#define NSTAGE 3
#define SMEM_REQ (NSTAGE * STAGEB)     // 79872 B -> 2 CTA/SM
#define DELTA1 3.0e-3f

__device__ int      g_done, g_done2, g_cnt1, g_cnt2;
__device__ float    g_Wp[NEXP * KDIM];          // fragment-packed W
__device__ float    g_part[NCTA * NEXP];
__device__ int      g_list1[NTOK], g_list2[NTOK];
__device__ unsigned g_cand[NTOK];

__device__ __forceinline__ void mma8(float* d, uint32_t a0, uint32_t a1,
                                     uint32_t a2, uint32_t a3,
                                     uint32_t b0, uint32_t b1) {
    asm volatile("mma.sync.aligned.m16n8k8.row.col.f32.tf32.tf32.f32 "
                 "{%0,%1,%2,%3},{%4,%5,%6,%7},{%8,%9},{%0,%1,%2,%3};"
                 : "+f"(d[0]), "+f"(d[1]), "+f"(d[2]), "+f"(d[3])
                 : "r"(a0), "r"(a1), "r"(a2), "r"(a3), "r"(b0), "r"(b1));
}
__device__ __forceinline__ void cp16(uint32_t s, const void* g) {
    asm volatile("cp.async.cg.shared.global [%0], [%1], 16;\n" :: "r"(s), "l"(g));
}
#define CP_COMMIT() asm volatile("cp.async.commit_group;\n")
#define CP_WAIT(n)  asm volatile("cp.async.wait_group %0;\n" :: "n"(n))

// ---- prep: pack W into per-chunk fragment-contiguous layout + reset ----
// pos(c,s,j,t,p) = c*2048 + (s*8+j)*64 + t*2 + p  holds
//   W[e = j*8 + t/4][k = c*32 + s*8 + (t&3) + 4p]
__global__ void prep_kernel(const float* __restrict__ W) {
    int pi = blockIdx.x * blockDim.x + threadIdx.x;     // 65536 pairs
    if (pi < NEXP * KDIM / 2) {
        int c = pi >> 10, rem = pi & 1023;
        int sj = rem >> 5, t = rem & 31;
        int e = (sj & 7) * 8 + (t >> 2);
        int k = c * 32 + (sj >> 3) * 8 + (t & 3);
        g_Wp[2 * pi]     = W[(size_t)e * KDIM + k];
        g_Wp[2 * pi + 1] = W[(size_t)e * KDIM + k + 4];
    }
    if (pi == 0) { g_done = 0; g_done2 = 0; g_cnt1 = 0; g_cnt2 = 0; }
}

__global__ void __launch_bounds__(NTHR, 2)
fused_kernel(const float* __restrict__ x, const float* __restrict__ W,
             float* __restrict__ out) {
    extern __shared__ float sm[];
    const uint32_t smb = (uint32_t)__cvta_generic_to_shared(sm);
    const int tid = threadIdx.x;
    const int wid = tid >> 5, lane = tid & 31;
    const int lq = lane & 3, lr = lane >> 2;
    const int tile = wid >> 1;          // m16 tile 0..7
    const int half = wid & 1;           // expert half: experts half*32..+31
    const int r0 = tile * 16 + lr;

    // ================= PHASE A: GEMM tile =================
    const float* xg = x + (size_t)blockIdx.x * MTILE * KDIM;

    auto issue_chunk = [&](int c) {
        uint32_t st = smb + (uint32_t)((c % NSTAGE) * STAGEB);
        #pragma unroll
        for (int v = 0; v < 2; v++) {                 // x: 128 rows x 8 f4
            int fi = tid + NTHR * v;
            int r = fi >> 3, j = fi & 7;
            cp16(st + (uint32_t)(r * 144 + j * 16),
                 xg + (size_t)r * KDIM + c * CK + j * 4);
        }
        cp16(st + XB + (uint32_t)tid * 16, g_Wp + (size_t)c * 2048 + tid * 4);
        CP_COMMIT();
    };

    float acc[4][4];
    #pragma unroll
    for (int j = 0; j < 4; j++)
        #pragma unroll
        for (int v = 0; v < 4; v++) acc[j][v] = 0.0f;

    issue_chunk(0); issue_chunk(1);

    for (int c = 0; c < NCHUNK; c++) {
        if (c < NCHUNK - 2) CP_WAIT(1);
        else                CP_WAIT(0);
        __syncthreads();
        if (c + 2 < NCHUNK) issue_chunk(c + 2);

        const float* xb = sm + (c % NSTAGE) * STAGEW;
        const float* wb = xb + XB / 4;
        #pragma unroll
        for (int s = 0; s < 4; s++) {
            const float* xr = xb + r0 * RWX + s * 8 + lq;
            uint32_t a0 = __float_as_uint(xr[0]);
            uint32_t a1 = __float_as_uint(xr[8 * RWX]);
            uint32_t a2 = __float_as_uint(xr[4]);
            uint32_t a3 = __float_as_uint(xr[8 * RWX + 4]);
            #pragma unroll
            for (int jj = 0; jj < 4; jj++) {
                float2 b = *(const float2*)(wb + (s * 8 + half * 4 + jj) * 64 + lane * 2);
                mma8(acc[jj], a0, a1, a2, a3,
                     __float_as_uint(b.x), __float_as_uint(b.y));
            }
        }
    }
    __syncthreads();

    // ---- epilogue overlay: sc[128][65], mm[128], iz[128], red[8][64] ----
    float* sc = sm;
    float* mm = sc + 128 * 65;
    float* iz = mm + 128;
    float* red = iz + 128;

    #pragma unroll
    for (int jj = 0; jj < 4; jj++) {
        int cb = (half * 4 + jj) * 8;
        sc[r0 * 65 + cb + 2 * lq]           = acc[jj][0];
        sc[r0 * 65 + cb + 2 * lq + 1]       = acc[jj][1];
        sc[(r0 + 8) * 65 + cb + 2 * lq]     = acc[jj][2];
        sc[(r0 + 8) * 65 + cb + 2 * lq + 1] = acc[jj][3];
    }
    __syncthreads();

    if (tid < 128) {    // one token per thread: top-4, softmax, ambiguity routing
        const int t = tid;
        const float* row = sc + t * 65;
        float m[4] = {-3e38f, -3e38f, -3e38f, -3e38f};
        int   id[4] = {0, 0, 0, 0};
        #pragma unroll 8
        for (int e = 0; e < 64; e++) {
            float v = row[e];
            if (v > m[0])      { m[3]=m[2]; id[3]=id[2]; m[2]=m[1]; id[2]=id[1];
                                 m[1]=m[0]; id[1]=id[0]; m[0]=v; id[0]=e; }
            else if (v > m[1]) { m[3]=m[2]; id[3]=id[2]; m[2]=m[1]; id[2]=id[1];
                                 m[1]=v; id[1]=e; }
            else if (v > m[2]) { m[3]=m[2]; id[3]=id[2]; m[2]=v; id[2]=e; }
            else if (v > m[3]) { m[3]=v; id[3]=e; }
        }
        float Z = 0.0f;
        #pragma unroll 8
        for (int e = 0; e < 64; e++) Z += __expf(row[e] - m[0]);
        mm[t] = m[0];
        iz[t] = 1.0f / Z;

        float e2 = __expf(m[1] - m[0]);
        float w1 = 1.0f / (1.0f + e2);
        size_t T = (size_t)blockIdx.x * MTILE + t;
        out[2 * T]     = (float)id[0];
        out[2 * T + 1] = (float)id[1];
        out[2 * (size_t)NTOK + 2 * T]     = w1;
        out[2 * (size_t)NTOK + 2 * T + 1] = e2 * w1;

        if ((m[0] - m[1]) < DELTA1 || (m[1] - m[2]) < DELTA1) {
            if ((m[1] - m[3]) < DELTA1) {
                int q = atomicAdd(&g_cnt2, 1);
                g_list2[q] = (int)T;
            } else {
                int q = atomicAdd(&g_cnt1, 1);
                g_list1[q] = (int)T;
                g_cand[q] = (unsigned)id[0] | ((unsigned)id[1] << 8) |
                            ((unsigned)id[2] << 16) | ((unsigned)id[3] << 24);
            }
        }
    }
    __syncthreads();

    {   // deterministic per-CTA expert-usage partials (8 segs x 16 tokens)
        const int e = tid & 63, seg = tid >> 6;
        float s = 0.0f;
        for (int t = seg * 16; t < seg * 16 + 16; t++)
            s += __expf(sc[t * 65 + e] - mm[t]) * iz[t];
        red[seg * 64 + e] = s;
    }
    __syncthreads();
    if (tid < NEXP) {
        float s = 0.0f;
        #pragma unroll
        for (int g = 0; g < 8; g++) s += red[g * 64 + tid];
        g_part[blockIdx.x * NEXP + tid] = s;
    }

    // ================= grid-wide barrier =================
    __threadfence();
    __syncthreads();
    if (tid == 0) {
        atomicAdd(&g_done, 1);
        while (atomicAdd(&g_done, 0) < NCTA) __nanosleep(128);
    }
    __syncthreads();
    __threadfence();

    // ================= PHASE B =================
    if (blockIdx.x == 0) {   // aux loss
        const int e = tid & 63, seg = tid >> 6;      // 8 segs x 32 CTAs
        float s = 0.0f;
        for (int c = seg * 32; c < seg * 32 + 32; c++)
            s += g_part[c * NEXP + e];
        sm[tid] = s;
        __syncthreads();
        if (tid < 64) {
            float u = 0.0f;
            #pragma unroll
            for (int g = 0; g < 8; g++) u += sm[g * 64 + tid];
            u *= (1.0f / (float)NTOK);
            sm[512 + tid] = u * u;
        }
        __syncthreads();
        if (tid < 32) {
            float v = sm[512 + tid] + sm[512 + tid + 32];
            #pragma unroll
            for (int o = 16; o > 0; o >>= 1) v += __shfl_xor_sync(0xffffffffu, v, o);
            if (tid == 0) out[131072] = 64.0f * v;
        }
        __syncthreads();
    }

    // fp64 recompute of top-4 candidates: 4 token-groups x 4 candidate-warps
    {
        static __shared__ double sv[16];
        static __shared__ int    se[16];
        const int n = g_cnt1;
        const int grp = wid >> 2;                     // 0..3
        for (int bq = blockIdx.x; bq < n; bq += 4 * NCTA) {
            const int q = bq + grp * NCTA;
            const bool valid = (q < n);
            int tok = 0, e = 0;
            double s = 0.0;
            if (valid) {
                tok = g_list1[q];
                e = (int)((g_cand[q] >> (8 * (wid & 3))) & 255u);
                const float* xr = x + (size_t)tok * KDIM;
                const float* wr = W + (size_t)e * KDIM;
                double c0 = 0.0, c1 = 0.0;
                #pragma unroll 2
                for (int j = 0; j < 64; j += 2) {
                    c0 += (double)xr[(j + 0) * 32 + lane] * (double)wr[(j + 0) * 32 + lane];
                    c1 += (double)xr[(j + 1) * 32 + lane] * (double)wr[(j + 1) * 32 + lane];
                }
                s = c0 + c1;
            }
            #pragma unroll
            for (int o = 16; o > 0; o >>= 1) s += __shfl_xor_sync(0xffffffffu, s, o);
            if (lane == 0) { sv[wid] = s; se[wid] = e; }
            __syncthreads();
            if ((tid & 127) == 0) {
                const int g = tid >> 7;               // 0..3
                const int qq = bq + g * NCTA;
                if (qq < n) {
                    const int tk = g_list1[qq];
                    const double* v = sv + g * 4;
                    const int*    ee = se + g * 4;
                    int b1 = 0;
                    for (int k = 1; k < 4; k++)
                        if (v[k] > v[b1] || (v[k] == v[b1] && ee[k] < ee[b1])) b1 = k;
                    int b2 = (b1 == 0) ? 1 : 0;
                    for (int k = 0; k < 4; k++) {
                        if (k == b1) continue;
                        if (v[k] > v[b2] || (v[k] == v[b2] && ee[k] < ee[b2])) b2 = k;
                    }
                    double e2 = exp(v[b2] - v[b1]);
                    double w1 = 1.0 / (1.0 + e2);
                    out[2 * (size_t)tk]     = (float)ee[b1];
                    out[2 * (size_t)tk + 1] = (float)ee[b2];
                    out[2 * (size_t)NTOK + 2 * (size_t)tk]     = (float)w1;
                    out[2 * (size_t)NTOK + 2 * (size_t)tk + 1] = (float)(e2 * w1);
                }
            }
            __syncthreads();
        }
    }

    // rare full-64 fp64 tokens: warp wid -> experts wid*4..wid*4+3
    {
        static __shared__ double sh[64];
        const int n2 = g_cnt2;
        for (int q = blockIdx.x; q < n2; q += NCTA) {
            const int tok = g_list2[q];
            const float* xr = x + (size_t)tok * KDIM;
            #pragma unroll 1
            for (int e4 = 0; e4 < 4; e4++) {
                const int e = wid * 4 + e4;
                const float* wr = W + (size_t)e * KDIM;
                double c0 = 0.0, c1 = 0.0;
                #pragma unroll 2
                for (int j = 0; j < 64; j += 2) {
                    c0 += (double)xr[(j + 0) * 32 + lane] * (double)wr[(j + 0) * 32 + lane];
                    c1 += (double)xr[(j + 1) * 32 + lane] * (double)wr[(j + 1) * 32 + lane];
                }
                double s = c0 + c1;
                #pragma unroll
                for (int o = 16; o > 0; o >>= 1) s += __shfl_xor_sync(0xffffffffu, s, o);
                if (lane == 0) sh[e] = s;
            }
            __syncthreads();
            if (tid == 0) {
                double m1 = -1e300, m2 = -1e300; int i1 = 0, i2 = 0;
                for (int e = 0; e < 64; e++)
                    if (sh[e] > m1) { m1 = sh[e]; i1 = e; }
                for (int e = 0; e < 64; e++) {
                    if (e == i1) continue;
                    if (sh[e] > m2) { m2 = sh[e]; i2 = e; }
                }
                double e2 = exp(m2 - m1);
                double w1 = 1.0 / (1.0 + e2);
                out[2 * (size_t)tok]     = (float)i1;
                out[2 * (size_t)tok + 1] = (float)i2;
                out[2 * (size_t)NTOK + 2 * (size_t)tok]     = (float)w1;
                out[2 * (size_t)NTOK + 2 * (size_t)tok + 1] = (float)(e2 * w1);
            }
            __syncthreads();
        }
    }

    // ================= PHASE C: reset for next graph replay =================
    __syncthreads();
    if (tid == 0) {
        __threadfence();
        int v = atomicAdd(&g_done2, 1);
        if (v == NCTA - 1) {
            g_done = 0; g_done2 = 0; g_cnt1 = 0; g_cnt2 = 0;
            __threadfence();
        }
    }
}

extern "C" void kernel_launch(void* const* d_in, const int* in_sizes, int n_in,
                              void* d_out, int out_size) {
    const float* x = (const float*)d_in[0];
    const float* W = (const float*)d_in[1];
    float* out = (float*)d_out;
    cudaFuncSetAttribute(fused_kernel, cudaFuncAttributeMaxDynamicSharedMemorySize,
                         SMEM_REQ);
    prep_kernel<<<256, 256>>>(W);
    fused_kernel<<<NCTA, NTHR, SMEM_REQ>>>(x, W, out);
}

// round 16
// speedup vs baseline: 1.5185x; 1.0582x over previous
#include <cuda_runtime.h>
#include <cuda_fp16.h>
#include <cstdint>

// Router_63900523430579 (GB300/sm_103): scores = x[32768,2048] @ W[64,2048]^T
// Fused persistent kernel: fp16 mma.sync m16n8k16 (halved MMA count vs tf32),
// f32 accumulate; x converted f32->fp16 in staging; W pre-packed fp16 in
// fragment order. Top-2 epilogue + grid barrier + fp64 fixup + aux loss.
// out f32: [0,65536) top2 idx ; [65536,131072) top2 weights ; [131072] aux loss

#define KDIM   2048
#define NTOK   32768
#define NEXP   64
#define MTILE  128
#define NCTA   (NTOK / MTILE)          // 256
#define NTHR   512
#define CK     32                      // K floats per chunk
#define NCHUNK (KDIM / CK)             // 64
#define RXU    20                      // x row stride in u32 (fp16x2) units
#define XU     (MTILE * RXU)           // 2560 u32 x per stage
#define WU     1024                    // packed W u32 per chunk
#define STAGEU (XU + WU)               // 3584 u32 = 14336 B
#define SMEM_REQ 37376                 // max(2*14336, epilogue overlay 36352)+pad
#define DELTA1 3.5e-3f

__device__ int      g_done, g_done2, g_cnt1, g_cnt2;
__device__ uint32_t g_Wp16[NEXP * KDIM / 2];    // fp16x2, fragment-packed
__device__ float    g_part[NCTA * NEXP];
__device__ int      g_list1[NTOK], g_list2[NTOK];
__device__ unsigned g_cand[NTOK];

__device__ __forceinline__ void mma16(float* d, uint32_t a0, uint32_t a1,
                                      uint32_t a2, uint32_t a3,
                                      uint32_t b0, uint32_t b1) {
    asm volatile("mma.sync.aligned.m16n8k16.row.col.f32.f16.f16.f32 "
                 "{%0,%1,%2,%3},{%4,%5,%6,%7},{%8,%9},{%0,%1,%2,%3};"
                 : "+f"(d[0]), "+f"(d[1]), "+f"(d[2]), "+f"(d[3])
                 : "r"(a0), "r"(a1), "r"(a2), "r"(a3), "r"(b0), "r"(b1));
}
__device__ __forceinline__ uint32_t h2(float a, float b) {
    __half2 h = __floats2half2_rn(a, b);
    return *reinterpret_cast<uint32_t*>(&h);
}

// ---- prep: pack W to fp16 fragment order + reset counters ----
// u32 index u = c*1024 + (s*8+j)*64 + lane*2 + reg  holds fp16x2
//   { W[e][kk], W[e][kk+1] },  e = j*8 + lane/4,
//   kk = c*32 + s*16 + (lane%4)*2 + reg*8
__global__ void prep_kernel(const float* __restrict__ W) {
    int u = blockIdx.x * blockDim.x + threadIdx.x;      // 65536 u32
    if (u < NEXP * KDIM / 2) {
        int c = u >> 10, rem = u & 1023;
        int sj = rem >> 6, ln2 = rem & 63;
        int lane = ln2 >> 1, reg = ln2 & 1;
        int s = sj >> 3, j = sj & 7;
        int e = j * 8 + (lane >> 2);
        int kk = c * 32 + s * 16 + (lane & 3) * 2 + reg * 8;
        g_Wp16[u] = h2(W[(size_t)e * KDIM + kk], W[(size_t)e * KDIM + kk + 1]);
    }
    if (u == 0) { g_done = 0; g_done2 = 0; g_cnt1 = 0; g_cnt2 = 0; }
}

__global__ void __launch_bounds__(NTHR, 2)
fused_kernel(const float* __restrict__ x, const float* __restrict__ W,
             float* __restrict__ out) {
    extern __shared__ float smf[];
    uint32_t* smu = (uint32_t*)smf;
    const int tid = threadIdx.x;
    const int wid = tid >> 5, lane = tid & 31;
    const int lq = lane & 3, lr = lane >> 2;
    const int tile = wid >> 1;          // m16 tile 0..7
    const int half = wid & 1;           // expert half
    const int r0 = tile * 16 + lr;

    // ================= PHASE A: GEMM tile =================
    const float* xg = x + (size_t)blockIdx.x * MTILE * KDIM;
    const int sr = tid >> 2, sq = tid & 3;   // staging: row, quad

    float4 rx0, rx1; uint2 rw;
    auto ldg_chunk = [&](int c) {
        const float* p = xg + (size_t)sr * KDIM + c * CK + sq * 8;
        rx0 = *(const float4*)(p);
        rx1 = *(const float4*)(p + 4);
        rw  = *(const uint2*)(g_Wp16 + (size_t)c * WU + tid * 2);
    };
    auto sts_chunk = [&](int c) {
        uint32_t* st = smu + (c & 1) * STAGEU;
        uint4 v;
        v.x = h2(rx0.x, rx0.y); v.y = h2(rx0.z, rx0.w);
        v.z = h2(rx1.x, rx1.y); v.w = h2(rx1.z, rx1.w);
        *(uint4*)(st + sr * RXU + sq * 4) = v;
        *(uint2*)(st + XU + tid * 2) = make_uint2(rw.x, rw.y);
    };

    float acc[4][4];
    #pragma unroll
    for (int j = 0; j < 4; j++)
        #pragma unroll
        for (int v = 0; v < 4; v++) acc[j][v] = 0.0f;

    ldg_chunk(0); sts_chunk(0); ldg_chunk(1);
    __syncthreads();

    for (int c = 0; c < NCHUNK; c++) {
        const uint32_t* xb = smu + (c & 1) * STAGEU;
        const uint32_t* wb = xb + XU;
        #pragma unroll
        for (int s = 0; s < 2; s++) {
            uint32_t a0 = xb[r0 * RXU + s * 8 + lq];
            uint32_t a1 = xb[(r0 + 8) * RXU + s * 8 + lq];
            uint32_t a2 = xb[r0 * RXU + s * 8 + lq + 4];
            uint32_t a3 = xb[(r0 + 8) * RXU + s * 8 + lq + 4];
            #pragma unroll
            for (int jj = 0; jj < 4; jj++) {
                const uint32_t* bp = wb + (s * 8 + half * 4 + jj) * 64 + lane * 2;
                mma16(acc[jj], a0, a1, a2, a3, bp[0], bp[1]);
            }
        }
        if (c + 1 < NCHUNK) sts_chunk(c + 1);
        __syncthreads();
        if (c + 2 < NCHUNK) ldg_chunk(c + 2);
    }

    // ---- epilogue overlay: sc[128][65], mm[128], iz[128], red[8][64] ----
    float* sc = smf;
    float* mm = sc + 128 * 65;
    float* iz = mm + 128;
    float* red = iz + 128;

    #pragma unroll
    for (int jj = 0; jj < 4; jj++) {
        int cb = (half * 4 + jj) * 8;
        sc[r0 * 65 + cb + 2 * lq]           = acc[jj][0];
        sc[r0 * 65 + cb + 2 * lq + 1]       = acc[jj][1];
        sc[(r0 + 8) * 65 + cb + 2 * lq]     = acc[jj][2];
        sc[(r0 + 8) * 65 + cb + 2 * lq + 1] = acc[jj][3];
    }
    __syncthreads();

    if (tid < 128) {    // one token per thread: top-4, softmax, ambiguity routing
        const int t = tid;
        const float* row = sc + t * 65;
        float m[4] = {-3e38f, -3e38f, -3e38f, -3e38f};
        int   id[4] = {0, 0, 0, 0};
        #pragma unroll 8
        for (int e = 0; e < 64; e++) {
            float v = row[e];
            if (v > m[0])      { m[3]=m[2]; id[3]=id[2]; m[2]=m[1]; id[2]=id[1];
                                 m[1]=m[0]; id[1]=id[0]; m[0]=v; id[0]=e; }
            else if (v > m[1]) { m[3]=m[2]; id[3]=id[2]; m[2]=m[1]; id[2]=id[1];
                                 m[1]=v; id[1]=e; }
            else if (v > m[2]) { m[3]=m[2]; id[3]=id[2]; m[2]=v; id[2]=e; }
            else if (v > m[3]) { m[3]=v; id[3]=e; }
        }
        float Z = 0.0f;
        #pragma unroll 8
        for (int e = 0; e < 64; e++) Z += __expf(row[e] - m[0]);
        mm[t] = m[0];
        iz[t] = 1.0f / Z;

        float e2 = __expf(m[1] - m[0]);
        float w1 = 1.0f / (1.0f + e2);
        size_t T = (size_t)blockIdx.x * MTILE + t;
        out[2 * T]     = (float)id[0];
        out[2 * T + 1] = (float)id[1];
        out[2 * (size_t)NTOK + 2 * T]     = w1;
        out[2 * (size_t)NTOK + 2 * T + 1] = e2 * w1;

        if ((m[0] - m[1]) < DELTA1 || (m[1] - m[2]) < DELTA1) {
            if ((m[1] - m[3]) < DELTA1) {
                int q = atomicAdd(&g_cnt2, 1);
                g_list2[q] = (int)T;
            } else {
                int q = atomicAdd(&g_cnt1, 1);
                g_list1[q] = (int)T;
                g_cand[q] = (unsigned)id[0] | ((unsigned)id[1] << 8) |
                            ((unsigned)id[2] << 16) | ((unsigned)id[3] << 24);
            }
        }
    }
    __syncthreads();

    {   // deterministic per-CTA expert-usage partials (8 segs x 16 tokens)
        const int e = tid & 63, seg = tid >> 6;
        float s = 0.0f;
        for (int t = seg * 16; t < seg * 16 + 16; t++)
            s += __expf(sc[t * 65 + e] - mm[t]) * iz[t];
        red[seg * 64 + e] = s;
    }
    __syncthreads();
    if (tid < NEXP) {
        float s = 0.0f;
        #pragma unroll
        for (int g = 0; g < 8; g++) s += red[g * 64 + tid];
        g_part[blockIdx.x * NEXP + tid] = s;
    }

    // ================= grid-wide barrier =================
    __threadfence();
    __syncthreads();
    if (tid == 0) {
        atomicAdd(&g_done, 1);
        while (atomicAdd(&g_done, 0) < NCTA) __nanosleep(128);
    }
    __syncthreads();
    __threadfence();

    // ================= PHASE B =================
    if (blockIdx.x == 0) {   // aux loss
        const int e = tid & 63, seg = tid >> 6;      // 8 segs x 32 CTAs
        float s = 0.0f;
        for (int c = seg * 32; c < seg * 32 + 32; c++)
            s += g_part[c * NEXP + e];
        smf[tid] = s;
        __syncthreads();
        if (tid < 64) {
            float u = 0.0f;
            #pragma unroll
            for (int g = 0; g < 8; g++) u += smf[g * 64 + tid];
            u *= (1.0f / (float)NTOK);
            smf[512 + tid] = u * u;
        }
        __syncthreads();
        if (tid < 32) {
            float v = smf[512 + tid] + smf[512 + tid + 32];
            #pragma unroll
            for (int o = 16; o > 0; o >>= 1) v += __shfl_xor_sync(0xffffffffu, v, o);
            if (tid == 0) out[131072] = 64.0f * v;
        }
        __syncthreads();
    }

    // fp64 recompute of top-4 candidates: 4 token-groups x 4 candidate-warps
    {
        static __shared__ double sv[16];
        static __shared__ int    se[16];
        const int n = g_cnt1;
        const int grp = wid >> 2;                     // 0..3
        for (int bq = blockIdx.x; bq < n; bq += 4 * NCTA) {
            const int q = bq + grp * NCTA;
            const bool valid = (q < n);
            int tok = 0, e = 0;
            double s = 0.0;
            if (valid) {
                tok = g_list1[q];
                e = (int)((g_cand[q] >> (8 * (wid & 3))) & 255u);
                const float* xr = x + (size_t)tok * KDIM;
                const float* wr = W + (size_t)e * KDIM;
                double c0 = 0.0, c1 = 0.0;
                #pragma unroll 2
                for (int j = 0; j < 64; j += 2) {
                    c0 += (double)xr[(j + 0) * 32 + lane] * (double)wr[(j + 0) * 32 + lane];
                    c1 += (double)xr[(j + 1) * 32 + lane] * (double)wr[(j + 1) * 32 + lane];
                }
                s = c0 + c1;
            }
            #pragma unroll
            for (int o = 16; o > 0; o >>= 1) s += __shfl_xor_sync(0xffffffffu, s, o);
            if (lane == 0) { sv[wid] = s; se[wid] = e; }
            __syncthreads();
            if ((tid & 127) == 0) {
                const int g = tid >> 7;               // 0..3
                const int qq = bq + g * NCTA;
                if (qq < n) {
                    const int tk = g_list1[qq];
                    const double* v = sv + g * 4;
                    const int*    ee = se + g * 4;
                    int b1 = 0;
                    for (int k = 1; k < 4; k++)
                        if (v[k] > v[b1] || (v[k] == v[b1] && ee[k] < ee[b1])) b1 = k;
                    int b2 = (b1 == 0) ? 1 : 0;
                    for (int k = 0; k < 4; k++) {
                        if (k == b1) continue;
                        if (v[k] > v[b2] || (v[k] == v[b2] && ee[k] < ee[b2])) b2 = k;
                    }
                    double e2 = exp(v[b2] - v[b1]);
                    double w1 = 1.0 / (1.0 + e2);
                    out[2 * (size_t)tk]     = (float)ee[b1];
                    out[2 * (size_t)tk + 1] = (float)ee[b2];
                    out[2 * (size_t)NTOK + 2 * (size_t)tk]     = (float)w1;
                    out[2 * (size_t)NTOK + 2 * (size_t)tk + 1] = (float)(e2 * w1);
                }
            }
            __syncthreads();
        }
    }

    // rare full-64 fp64 tokens: warp wid -> experts wid*4..wid*4+3
    {
        static __shared__ double sh[64];
        const int n2 = g_cnt2;
        for (int q = blockIdx.x; q < n2; q += NCTA) {
            const int tok = g_list2[q];
            const float* xr = x + (size_t)tok * KDIM;
            #pragma unroll 1
            for (int e4 = 0; e4 < 4; e4++) {
                const int e = wid * 4 + e4;
                const float* wr = W + (size_t)e * KDIM;
                double c0 = 0.0, c1 = 0.0;
                #pragma unroll 2
                for (int j = 0; j < 64; j += 2) {
                    c0 += (double)xr[(j + 0) * 32 + lane] * (double)wr[(j + 0) * 32 + lane];
                    c1 += (double)xr[(j + 1) * 32 + lane] * (double)wr[(j + 1) * 32 + lane];
                }
                double s = c0 + c1;
                #pragma unroll
                for (int o = 16; o > 0; o >>= 1) s += __shfl_xor_sync(0xffffffffu, s, o);
                if (lane == 0) sh[e] = s;
            }
            __syncthreads();
            if (tid == 0) {
                double m1 = -1e300, m2 = -1e300; int i1 = 0, i2 = 0;
                for (int e = 0; e < 64; e++)
                    if (sh[e] > m1) { m1 = sh[e]; i1 = e; }
                for (int e = 0; e < 64; e++) {
                    if (e == i1) continue;
                    if (sh[e] > m2) { m2 = sh[e]; i2 = e; }
                }
                double e2 = exp(m2 - m1);
                double w1 = 1.0 / (1.0 + e2);
                out[2 * (size_t)tok]     = (float)i1;
                out[2 * (size_t)tok + 1] = (float)i2;
                out[2 * (size_t)NTOK + 2 * (size_t)tok]     = (float)w1;
                out[2 * (size_t)NTOK + 2 * (size_t)tok + 1] = (float)(e2 * w1);
            }
            __syncthreads();
        }
    }

    // ================= PHASE C: reset for next graph replay =================
    __syncthreads();
    if (tid == 0) {
        __threadfence();
        int v = atomicAdd(&g_done2, 1);
        if (v == NCTA - 1) {
            g_done = 0; g_done2 = 0; g_cnt1 = 0; g_cnt2 = 0;
            __threadfence();
        }
    }
}

extern "C" void kernel_launch(void* const* d_in, const int* in_sizes, int n_in,
                              void* d_out, int out_size) {
    const float* x = (const float*)d_in[0];
    const float* W = (const float*)d_in[1];
    float* out = (float*)d_out;
    cudaFuncSetAttribute(fused_kernel, cudaFuncAttributeMaxDynamicSharedMemorySize,
                         SMEM_REQ);
    prep_kernel<<<256, 256>>>(W);
    fused_kernel<<<NCTA, NTHR, SMEM_REQ>>>(x, W, out);
}